// round 1
// baseline (speedup 1.0000x reference)
#include <cuda_runtime.h>
#include <math.h>

#define Bc 4
#define Nc 512
#define Cc 64
#define Hc 8
#define Fc 8

typedef unsigned long long u64;

// ---------------- scratch (device globals: no allocs allowed) ----------------
__device__ float  xp_g[Bc * Nc * Cc];            // projected nodes (b,n,h,f)
__device__ float  ssrc_g[Bc * Hc * Nc];          // (b,h,n)
__device__ float  sdst_g[Bc * Hc * Nc];          // (b,h,n)
__device__ float2 W2T_g[32 * 64];                // paired We: [c2][k] = {We[2c2][k], We[2c2+1][k]}
__device__ float  SE_g[(size_t)Bc * Hc * Nc * Nc]; // edge scores laid out [b][h][p=j][q=i]

__device__ __forceinline__ float2 u2f(u64 v) {
    float2 r;
    r.x = __uint_as_float((unsigned)(v & 0xffffffffu));
    r.y = __uint_as_float((unsigned)(v >> 32));
    return r;
}

// ---------------- kernel 0: build paired-We layout ----------------
__global__ void k_w2t(const float* __restrict__ We) {
    int idx = blockIdx.x * 256 + threadIdx.x;    // 0..2047
    int c2 = idx >> 6, k = idx & 63;
    W2T_g[idx] = make_float2(We[(2 * c2) * 64 + k], We[(2 * c2 + 1) * 64 + k]);
}

// ---------------- kernel 1: xp = x@W, s_src, s_dst ----------------
__global__ void k_proj(const float* __restrict__ x, const float* __restrict__ W,
                       const float* __restrict__ a_src, const float* __restrict__ a_dst) {
    __shared__ float xs[64];
    __shared__ float xps[64];
    int row = blockIdx.x;                        // b*512 + n
    int t = threadIdx.x;                         // 64 threads
    xs[t] = x[row * 64 + t];
    __syncthreads();
    float acc = 0.f;
#pragma unroll
    for (int c = 0; c < 64; c++) acc = fmaf(xs[c], W[c * 64 + t], acc);
    xps[t] = acc;
    xp_g[row * 64 + t] = acc;
    __syncthreads();
    if (t < 8) {
        float ss = 0.f, sd = 0.f;
#pragma unroll
        for (int f = 0; f < 8; f++) {
            float v = xps[t * 8 + f];
            ss = fmaf(v, a_src[t * 8 + f], ss);
            sd = fmaf(v, a_dst[t * 8 + f], sd);
        }
        int b = row >> 9, n = row & 511;
        ssrc_g[(b * 8 + t) * 512 + n] = ss;
        sdst_g[(b * 8 + t) * 512 + n] = sd;
    }
}

// ---------------- kernel 2: ep = e@We, e_out = elu(ep), edge scores ----------------
// Block: 128 threads, tile = 8 i x 8 j = 64 GEMM rows, full 64 output cols.
// Thread (ty,tx): rows ty*8..+7 (row = ii*8+jj, so ii=ty, jj=rr), cols tx*4..+3.
// Accumulators are fp32x2 packed over c-parity -> 2x fp32 FMA rate.
__global__ void __launch_bounds__(128, 4)
k_edge(const float* __restrict__ e, const float* __restrict__ a_edge,
       float* __restrict__ e_out) {
    __shared__ __align__(16) float Es[64 * 64];      // e tile, row-major [r][c]
    __shared__ __align__(16) float Ws[32 * 64 * 2];  // W pairs, [c2][k] as float2
    __shared__ float SCs[512];                       // scores [h][jj][ii]

    int t = threadIdx.x;
    int b = blockIdx.z, i0 = blockIdx.y * 8, j0 = blockIdx.x * 8;

    // stage W pairs (16KB straight copy)
    {
        const float4* Wg4 = (const float4*)W2T_g;
        float4* Ws4 = (float4*)Ws;
#pragma unroll
        for (int u = 0; u < 8; u++) Ws4[t + 128 * u] = Wg4[t + 128 * u];
    }
    // stage e tile (16KB, coalesced float4)
    {
        const float4* eg4 = (const float4*)e;
        float4* Es4 = (float4*)Es;
#pragma unroll
        for (int u = 0; u < 8; u++) {
            int F = t + 128 * u;
            int r = F >> 4, c4 = F & 15;
            int ii = r >> 3, jj = r & 7;
            size_t rowbase = (size_t)((b * 512 + i0 + ii) * 512 + (j0 + jj)) * 16;
            Es4[F] = eg4[rowbase + c4];
        }
    }
    __syncthreads();

    int ty = t >> 4, tx = t & 15;
    u64 acc[8][4];
#pragma unroll
    for (int r = 0; r < 8; r++)
#pragma unroll
        for (int k = 0; k < 4; k++) acc[r][k] = 0ull;

    const u64* Es64 = (const u64*)Es;   // [r][c2] pairs
    const u64* Ws64 = (const u64*)Ws;   // [c2][k] pairs

#pragma unroll 4
    for (int c2 = 0; c2 < 32; c2++) {
        ulonglong2 wa = ((const ulonglong2*)Ws64)[(c2 * 64 + tx * 4) >> 1];
        ulonglong2 wb = ((const ulonglong2*)Ws64)[((c2 * 64 + tx * 4) >> 1) + 1];
        u64 w0 = wa.x, w1 = wa.y, w2 = wb.x, w3 = wb.y;
#pragma unroll
        for (int rr = 0; rr < 8; rr++) {
            u64 ev = Es64[(ty * 8 + rr) * 32 + c2];   // half-warp broadcast
            asm("fma.rn.f32x2 %0, %1, %2, %0;" : "+l"(acc[rr][0]) : "l"(ev), "l"(w0));
            asm("fma.rn.f32x2 %0, %1, %2, %0;" : "+l"(acc[rr][1]) : "l"(ev), "l"(w1));
            asm("fma.rn.f32x2 %0, %1, %2, %0;" : "+l"(acc[rr][2]) : "l"(ev), "l"(w2));
            asm("fma.rn.f32x2 %0, %1, %2, %0;" : "+l"(acc[rr][3]) : "l"(ev), "l"(w3));
        }
    }

    // epilogue: elu -> e_out, head-score partials -> SCs -> SE_g (transposed)
    int h = tx >> 1, sub = tx & 1;
    float ae0 = a_edge[h * 8 + sub * 4 + 0];
    float ae1 = a_edge[h * 8 + sub * 4 + 1];
    float ae2 = a_edge[h * 8 + sub * 4 + 2];
    float ae3 = a_edge[h * 8 + sub * 4 + 3];
    float part[8];
#pragma unroll
    for (int rr = 0; rr < 8; rr++) {
        float2 p0 = u2f(acc[rr][0]), p1 = u2f(acc[rr][1]);
        float2 p2 = u2f(acc[rr][2]), p3 = u2f(acc[rr][3]);
        float v0 = p0.x + p0.y, v1 = p1.x + p1.y, v2 = p2.x + p2.y, v3 = p3.x + p3.y;
        part[rr] = v0 * ae0 + v1 * ae1 + v2 * ae2 + v3 * ae3;
        float4 o;
        o.x = (v0 > 0.f) ? v0 : expm1f(v0);
        o.y = (v1 > 0.f) ? v1 : expm1f(v1);
        o.z = (v2 > 0.f) ? v2 : expm1f(v2);
        o.w = (v3 > 0.f) ? v3 : expm1f(v3);
        int ii = ty, jj = rr;
        size_t m = (size_t)((b * 512 + i0 + ii) * 512 + (j0 + jj));
        ((float4*)(e_out + m * 64))[tx] = o;
    }
#pragma unroll
    for (int rr = 0; rr < 8; rr++)
        part[rr] += __shfl_xor_sync(0xffffffffu, part[rr], 1);
    if (sub == 0) {
#pragma unroll
        for (int rr = 0; rr < 8; rr++) SCs[h * 64 + rr * 8 + ty] = part[rr];
    }
    __syncthreads();
    {
        int idx = t * 4;                       // [h][jj][ii4]
        int hh = idx >> 6, jj = (idx >> 3) & 7, iq = idx & 7;
        float4 v = *(float4*)&SCs[idx];
        size_t o = ((size_t)((b * 8 + hh) * 512 + (j0 + jj))) * 512 + (size_t)(i0 + iq);
        *(float4*)&SE_g[o] = v;               // SE[b][h][p=j][q=i], 16B sector-aligned
    }
}

// ---------------- kernel 3: masked softmax + att@xp + residual + elu ----------------
// Block per (b,p), one warp per head.
__global__ void __launch_bounds__(256)
k_attn(const float* __restrict__ adj, const float* __restrict__ x,
       const float* __restrict__ bias, float* __restrict__ out) {
    int bp = blockIdx.x;
    int b = bp >> 9, p = bp & 511;
    int h = threadIdx.x >> 5, lane = threadIdx.x & 31;

    const float* SErow = SE_g + ((size_t)((b * 8 + h) * 512 + p)) * 512;
    const float* adjrow = adj + (size_t)(b * 512 + p) * 512;
    const float* sd = sdst_g + (b * 8 + h) * 512;
    float ssrc = ssrc_g[(b * 8 + h) * 512 + p];

    float sc[16];
    float mx = -3.0e38f;
#pragma unroll
    for (int tt = 0; tt < 16; tt++) {
        int q = lane + tt * 32;
        float a = adjrow[q];
        float s = ssrc + sd[q] + SErow[q];
        s = (s > 0.f) ? s : 0.2f * s;           // leaky_relu
        s = (a < 0.5f) ? -3.0e38f : s;          // mask
        sc[tt] = s;
        mx = fmaxf(mx, s);
    }
#pragma unroll
    for (int o = 16; o; o >>= 1) mx = fmaxf(mx, __shfl_xor_sync(0xffffffffu, mx, o));

    float sum = 0.f;
#pragma unroll
    for (int tt = 0; tt < 16; tt++) {
        float evv = (sc[tt] < -1.0e38f) ? 0.f : __expf(sc[tt] - mx);
        sc[tt] = evv;
        sum += evv;
    }
#pragma unroll
    for (int o = 16; o; o >>= 1) sum += __shfl_xor_sync(0xffffffffu, sum, o);

    float oa[8] = {0.f, 0.f, 0.f, 0.f, 0.f, 0.f, 0.f, 0.f};
#pragma unroll
    for (int tt = 0; tt < 16; tt++) {
        int q = lane + tt * 32;
        const float4* xq = (const float4*)(xp_g + (size_t)(b * 512 + q) * 64 + h * 8);
        float4 xa = xq[0], xb = xq[1];
        float w = sc[tt];
        oa[0] = fmaf(w, xa.x, oa[0]); oa[1] = fmaf(w, xa.y, oa[1]);
        oa[2] = fmaf(w, xa.z, oa[2]); oa[3] = fmaf(w, xa.w, oa[3]);
        oa[4] = fmaf(w, xb.x, oa[4]); oa[5] = fmaf(w, xb.y, oa[5]);
        oa[6] = fmaf(w, xb.z, oa[6]); oa[7] = fmaf(w, xb.w, oa[7]);
    }
#pragma unroll
    for (int o = 16; o; o >>= 1) {
#pragma unroll
        for (int f = 0; f < 8; f++) oa[f] += __shfl_xor_sync(0xffffffffu, oa[f], o);
    }

    __shared__ float os[64];
    if (lane == 0) {
        float inv = 1.f / sum;
#pragma unroll
        for (int f = 0; f < 8; f++) {
            float v = oa[f] * inv + x[(size_t)(b * 512 + p) * 64 + h * 8 + f] + bias[h * 8 + f];
            os[h * 8 + f] = (v > 0.f) ? v : expm1f(v);
        }
    }
    __syncthreads();
    if (threadIdx.x < 16)
        ((float4*)(out + (size_t)(b * 512 + p) * 64))[threadIdx.x] =
            ((const float4*)os)[threadIdx.x];
}

// ---------------- launch ----------------
extern "C" void kernel_launch(void* const* d_in, const int* in_sizes, int n_in,
                              void* d_out, int out_size) {
    const float* adj    = (const float*)d_in[0];
    const float* x      = (const float*)d_in[1];
    const float* e      = (const float*)d_in[2];
    const float* W      = (const float*)d_in[3];
    const float* We     = (const float*)d_in[4];
    const float* a_src  = (const float*)d_in[5];
    const float* a_dst  = (const float*)d_in[6];
    const float* a_edge = (const float*)d_in[7];
    const float* bias   = (const float*)d_in[8];

    float* out = (float*)d_out;
    float* e_out = out + Bc * Nc * Cc;   // out first, then e_out

    k_w2t<<<8, 256>>>(We);
    k_proj<<<Bc * Nc, 64>>>(x, W, a_src, a_dst);
    k_edge<<<dim3(Nc / 8, Nc / 8, Bc), 128>>>(e, a_edge, e_out);
    k_attn<<<Bc * Nc, 256>>>(adj, x, bias, out);
}

// round 2
// speedup vs baseline: 1.7025x; 1.7025x over previous
#include <cuda_runtime.h>
#include <cuda_bf16.h>
#include <math.h>

#define Bc 4
#define Nc 512
#define Cc 64
#define Hc 8
#define Fc 8

typedef unsigned int u32;

// ---------------- scratch (device globals: no allocs allowed) ----------------
__device__ float ssrc_g[Bc * Hc * Nc];             // (b,h,n)
__device__ float sdst_g[Bc * Hc * Nc];             // (b,h,n)
__device__ float xpT_g[Bc * Hc * Fc * Nc];         // projected nodes transposed [b][h][f][q]
__device__ float SE_g[(size_t)Bc * Hc * Nc * Nc];  // edge scores [b][h][p=j][q=i]
__device__ u32   Bp_hi_g[32 * 64];                 // B k-pairs: (We_hi[2k2][n], We_hi[2k2+1][n])
__device__ u32   Bp_lo_g[32 * 64];

// ---------------- kernel 0: build split-bf16 B (= We) in k-paired layout ----------------
__global__ void k_wprep(const float* __restrict__ We) {
    int idx = blockIdx.x * 256 + threadIdx.x;      // 0..2047
    int k2 = idx >> 6, n = idx & 63;
    float w0 = We[(2 * k2) * 64 + n];
    float w1 = We[(2 * k2 + 1) * 64 + n];
    __nv_bfloat16 h0 = __float2bfloat16_rn(w0);
    __nv_bfloat16 h1 = __float2bfloat16_rn(w1);
    __nv_bfloat16 l0 = __float2bfloat16_rn(w0 - __bfloat162float(h0));
    __nv_bfloat16 l1 = __float2bfloat16_rn(w1 - __bfloat162float(h1));
    __nv_bfloat162 ph = __halves2bfloat162(h0, h1);   // .x = low half
    __nv_bfloat162 pl = __halves2bfloat162(l0, l1);
    Bp_hi_g[idx] = *(u32*)&ph;
    Bp_lo_g[idx] = *(u32*)&pl;
}

// ---------------- kernel 1: xp = x@W (transposed out), s_src, s_dst ----------------
__global__ void k_proj(const float* __restrict__ x, const float* __restrict__ W,
                       const float* __restrict__ a_src, const float* __restrict__ a_dst) {
    __shared__ float xs[64];
    __shared__ float xps[64];
    int row = blockIdx.x;                          // b*512 + n
    int t = threadIdx.x;                           // 64 threads
    xs[t] = x[row * 64 + t];
    __syncthreads();
    float acc = 0.f;
#pragma unroll
    for (int c = 0; c < 64; c++) acc = fmaf(xs[c], W[c * 64 + t], acc);
    xps[t] = acc;
    int b = row >> 9, n = row & 511;
    xpT_g[(b * 64 + t) * 512 + n] = acc;           // t = h*8+f
    __syncthreads();
    if (t < 8) {
        float ss = 0.f, sd = 0.f;
#pragma unroll
        for (int f = 0; f < 8; f++) {
            float v = xps[t * 8 + f];
            ss = fmaf(v, a_src[t * 8 + f], ss);
            sd = fmaf(v, a_dst[t * 8 + f], sd);
        }
        ssrc_g[(b * 8 + t) * 512 + n] = ss;
        sdst_g[(b * 8 + t) * 512 + n] = sd;
    }
}

// ---------------- kernel 2: ep = e@We via bf16-split HMMA; e_out = elu(ep); SE ----------------
// Block: 256 threads (8 warps). Tile: fixed j, 64 consecutive i rows, all 64 cols.
// GEMM row r corresponds to e[b, i0+r, j, :]. Warp (wm<2, wn<4): M-range wm*32..+31,
// N-range wn*16..+15 (heads wn*2+{0,1}). 3 MMAs per tile: eh*Wh + el*Wh + eh*Wl.
#define APAD 72   // halves per A row (64 data + 8 pad): conflict-free frag LDS
#define BPAD 72   // u32 per B row

__global__ void __launch_bounds__(256) k_edge(
    const float* __restrict__ e, const float* __restrict__ a_edge,
    float* __restrict__ e_out) {
    __shared__ __align__(16) __nv_bfloat16 Ah[64 * APAD];
    __shared__ __align__(16) __nv_bfloat16 Al[64 * APAD];
    __shared__ __align__(16) u32 Bh[32 * BPAD];
    __shared__ __align__(16) u32 Bl[32 * BPAD];
    __shared__ float SCs[8 * 64];

    int t = threadIdx.x;
    int i0 = blockIdx.x * 64;
    int j = blockIdx.y;
    int b = blockIdx.z;

    // stage B (8KB x2 from global, hot in L2)
#pragma unroll
    for (int u = 0; u < 8; u++) {
        int idx = t + 256 * u;                     // 2048
        int k2 = idx >> 6, n = idx & 63;
        Bh[k2 * BPAD + n] = Bp_hi_g[idx];
        Bl[k2 * BPAD + n] = Bp_lo_g[idx];
    }
    // stage e tile: 64 rows x 64 f32, convert to bf16 hi/lo
    {
        const float4* eg4 = (const float4*)e;
#pragma unroll
        for (int u = 0; u < 4; u++) {
            int F = t + 256 * u;                   // 1024 float4
            int r = F >> 4, c4 = F & 15;
            size_t grow = (size_t)((b * 512 + i0 + r) * 512 + j);
            float4 v = eg4[grow * 16 + c4];
            __nv_bfloat16 h0 = __float2bfloat16_rn(v.x), h1 = __float2bfloat16_rn(v.y);
            __nv_bfloat16 h2 = __float2bfloat16_rn(v.z), h3 = __float2bfloat16_rn(v.w);
            __nv_bfloat16 l0 = __float2bfloat16_rn(v.x - __bfloat162float(h0));
            __nv_bfloat16 l1 = __float2bfloat16_rn(v.y - __bfloat162float(h1));
            __nv_bfloat16 l2 = __float2bfloat16_rn(v.z - __bfloat162float(h2));
            __nv_bfloat16 l3 = __float2bfloat16_rn(v.w - __bfloat162float(h3));
            __nv_bfloat162 ph0 = __halves2bfloat162(h0, h1), ph1 = __halves2bfloat162(h2, h3);
            __nv_bfloat162 pl0 = __halves2bfloat162(l0, l1), pl1 = __halves2bfloat162(l2, l3);
            uint2 sh; sh.x = *(u32*)&ph0; sh.y = *(u32*)&ph1;
            uint2 sl; sl.x = *(u32*)&pl0; sl.y = *(u32*)&pl1;
            *(uint2*)&Ah[r * APAD + c4 * 4] = sh;
            *(uint2*)&Al[r * APAD + c4 * 4] = sl;
        }
    }
    __syncthreads();

    int w = t >> 5, lane = t & 31;
    int wm = w & 1, wn = w >> 1;                   // wm<2 (M), wn<4 (N)
    int g = lane >> 2, tg = lane & 3;

    float c[2][2][4];
#pragma unroll
    for (int mi = 0; mi < 2; mi++)
#pragma unroll
        for (int ni = 0; ni < 2; ni++)
#pragma unroll
            for (int q = 0; q < 4; q++) c[mi][ni][q] = 0.f;

#pragma unroll
    for (int kk = 0; kk < 4; kk++) {
        // B fragments: b0 k=2tg, b1 k=2tg+1 -> k2 = kk*8+tg; b2/b3 -> k2+4
        u32 bh0[2], bh1[2], bl0[2], bl1[2];
#pragma unroll
        for (int ni = 0; ni < 2; ni++) {
            int n = wn * 16 + ni * 8 + g;
            bh0[ni] = Bh[(kk * 8 + tg) * BPAD + n];
            bh1[ni] = Bh[(kk * 8 + tg + 4) * BPAD + n];
            bl0[ni] = Bl[(kk * 8 + tg) * BPAD + n];
            bl1[ni] = Bl[(kk * 8 + tg + 4) * BPAD + n];
        }
#pragma unroll
        for (int mi = 0; mi < 2; mi++) {
            int r0 = wm * 32 + mi * 16;
            int baseA = (r0 + g) * APAD + kk * 16 + 2 * tg;
            int baseB = (r0 + g + 8) * APAD + kk * 16 + 2 * tg;
            u32 ah0 = *(u32*)&Ah[baseA];
            u32 ah1 = *(u32*)&Ah[baseB];
            u32 ah2 = *(u32*)&Ah[baseA + 8];
            u32 ah3 = *(u32*)&Ah[baseB + 8];
            u32 al0 = *(u32*)&Al[baseA];
            u32 al1 = *(u32*)&Al[baseB];
            u32 al2 = *(u32*)&Al[baseA + 8];
            u32 al3 = *(u32*)&Al[baseB + 8];
#pragma unroll
            for (int ni = 0; ni < 2; ni++) {
                float* cc = c[mi][ni];
#define MMA(A0,A1,A2,A3,B0,B1) \
    asm volatile("mma.sync.aligned.m16n8k16.row.col.f32.bf16.bf16.f32 " \
        "{%0,%1,%2,%3}, {%4,%5,%6,%7}, {%8,%9}, {%0,%1,%2,%3};" \
        : "+f"(cc[0]), "+f"(cc[1]), "+f"(cc[2]), "+f"(cc[3]) \
        : "r"(A0), "r"(A1), "r"(A2), "r"(A3), "r"(B0), "r"(B1))
                MMA(ah0, ah1, ah2, ah3, bh0[ni], bh1[ni]);   // eh * Wh
                MMA(al0, al1, al2, al3, bh0[ni], bh1[ni]);   // el * Wh
                MMA(ah0, ah1, ah2, ah3, bl0[ni], bl1[ni]);   // eh * Wl
#undef MMA
            }
        }
    }

    // epilogue: elu -> e_out; head-dot partials -> SCs -> coalesced SE write
#pragma unroll
    for (int mi = 0; mi < 2; mi++) {
#pragma unroll
        for (int ni = 0; ni < 2; ni++) {
            int h = wn * 2 + ni;
            float ae0 = a_edge[h * 8 + 2 * tg];
            float ae1 = a_edge[h * 8 + 2 * tg + 1];
            float c0 = c[mi][ni][0], c1 = c[mi][ni][1];
            float c2 = c[mi][ni][2], c3 = c[mi][ni][3];
            int rA = wm * 32 + mi * 16 + g, rB = rA + 8;
            size_t mA = (size_t)((b * 512 + i0 + rA) * 512 + j);
            size_t mB = (size_t)((b * 512 + i0 + rB) * 512 + j);
            float2 oA, oB;
            oA.x = (c0 > 0.f) ? c0 : expm1f(c0);
            oA.y = (c1 > 0.f) ? c1 : expm1f(c1);
            oB.x = (c2 > 0.f) ? c2 : expm1f(c2);
            oB.y = (c3 > 0.f) ? c3 : expm1f(c3);
            *(float2*)&e_out[mA * 64 + h * 8 + 2 * tg] = oA;
            *(float2*)&e_out[mB * 64 + h * 8 + 2 * tg] = oB;
            float pA = c0 * ae0 + c1 * ae1;
            float pB = c2 * ae0 + c3 * ae1;
            pA += __shfl_xor_sync(0xffffffffu, pA, 1);
            pA += __shfl_xor_sync(0xffffffffu, pA, 2);
            pB += __shfl_xor_sync(0xffffffffu, pB, 1);
            pB += __shfl_xor_sync(0xffffffffu, pB, 2);
            if (tg == 0) {
                SCs[h * 64 + rA] = pA;
                SCs[h * 64 + rB] = pB;
            }
        }
    }
    __syncthreads();
    {
        int idx = t * 2;                           // 512 floats
        int h = idx >> 6, q = idx & 63;
        float2 v = *(float2*)&SCs[idx];
        size_t o = ((size_t)((b * 8 + h) * 512 + j)) * 512 + (size_t)(i0 + q);
        *(float2*)&SE_g[o] = v;                    // SE[b][h][p=j][q=i], coalesced
    }
}

// ---------------- kernel 3: masked softmax + att@xp + residual + elu ----------------
// Block per (b,p), one warp per head; each lane owns 4 consecutive q per step.
__global__ void __launch_bounds__(256) k_attn(
    const float* __restrict__ adj, const float* __restrict__ x,
    const float* __restrict__ bias, float* __restrict__ out) {
    int bp = blockIdx.x;
    int b = bp >> 9, p = bp & 511;
    int h = threadIdx.x >> 5, lane = threadIdx.x & 31;

    const float* SErow = SE_g + ((size_t)((b * 8 + h) * 512 + p)) * 512;
    const float* adjrow = adj + (size_t)(b * 512 + p) * 512;
    const float* sd = sdst_g + (b * 8 + h) * 512;
    float ssrc = ssrc_g[(b * 8 + h) * 512 + p];

    float4 sc[4];
    float mx = -3.0e38f;
#pragma unroll
    for (int tt = 0; tt < 4; tt++) {
        int q = 4 * lane + 128 * tt;
        float4 a = *(const float4*)&adjrow[q];
        float4 se = *(const float4*)&SErow[q];
        float4 sv = *(const float4*)&sd[q];
        float s0 = ssrc + sv.x + se.x; s0 = (s0 > 0.f) ? s0 : 0.2f * s0; s0 = (a.x < 0.5f) ? -3.0e38f : s0;
        float s1 = ssrc + sv.y + se.y; s1 = (s1 > 0.f) ? s1 : 0.2f * s1; s1 = (a.y < 0.5f) ? -3.0e38f : s1;
        float s2 = ssrc + sv.z + se.z; s2 = (s2 > 0.f) ? s2 : 0.2f * s2; s2 = (a.z < 0.5f) ? -3.0e38f : s2;
        float s3 = ssrc + sv.w + se.w; s3 = (s3 > 0.f) ? s3 : 0.2f * s3; s3 = (a.w < 0.5f) ? -3.0e38f : s3;
        sc[tt] = make_float4(s0, s1, s2, s3);
        mx = fmaxf(mx, fmaxf(fmaxf(s0, s1), fmaxf(s2, s3)));
    }
#pragma unroll
    for (int o = 16; o; o >>= 1) mx = fmaxf(mx, __shfl_xor_sync(0xffffffffu, mx, o));

    float sum = 0.f;
#pragma unroll
    for (int tt = 0; tt < 4; tt++) {
        float4 s = sc[tt];
        s.x = (s.x < -1.0e38f) ? 0.f : __expf(s.x - mx);
        s.y = (s.y < -1.0e38f) ? 0.f : __expf(s.y - mx);
        s.z = (s.z < -1.0e38f) ? 0.f : __expf(s.z - mx);
        s.w = (s.w < -1.0e38f) ? 0.f : __expf(s.w - mx);
        sc[tt] = s;
        sum += s.x + s.y + s.z + s.w;
    }
#pragma unroll
    for (int o = 16; o; o >>= 1) sum += __shfl_xor_sync(0xffffffffu, sum, o);

    const float* xpT = xpT_g + (size_t)(b * 64 + h * 8) * 512;
    float oa[8] = {0.f, 0.f, 0.f, 0.f, 0.f, 0.f, 0.f, 0.f};
#pragma unroll
    for (int tt = 0; tt < 4; tt++) {
        int q = 4 * lane + 128 * tt;
        float4 s = sc[tt];
#pragma unroll
        for (int f = 0; f < 8; f++) {
            float4 xv = *(const float4*)&xpT[f * 512 + q];   // coalesced over q
            oa[f] += s.x * xv.x + s.y * xv.y + s.z * xv.z + s.w * xv.w;
        }
    }
#pragma unroll
    for (int o = 16; o; o >>= 1) {
#pragma unroll
        for (int f = 0; f < 8; f++) oa[f] += __shfl_xor_sync(0xffffffffu, oa[f], o);
    }

    __shared__ float os[64];
    if (lane == 0) {
        float inv = 1.f / sum;
#pragma unroll
        for (int f = 0; f < 8; f++) {
            float v = oa[f] * inv + x[(size_t)(b * 512 + p) * 64 + h * 8 + f] + bias[h * 8 + f];
            os[h * 8 + f] = (v > 0.f) ? v : expm1f(v);
        }
    }
    __syncthreads();
    if (threadIdx.x < 16)
        ((float4*)(out + (size_t)(b * 512 + p) * 64))[threadIdx.x] =
            ((const float4*)os)[threadIdx.x];
}

// ---------------- launch ----------------
extern "C" void kernel_launch(void* const* d_in, const int* in_sizes, int n_in,
                              void* d_out, int out_size) {
    const float* adj    = (const float*)d_in[0];
    const float* x      = (const float*)d_in[1];
    const float* e      = (const float*)d_in[2];
    const float* W      = (const float*)d_in[3];
    const float* We     = (const float*)d_in[4];
    const float* a_src  = (const float*)d_in[5];
    const float* a_dst  = (const float*)d_in[6];
    const float* a_edge = (const float*)d_in[7];
    const float* bias   = (const float*)d_in[8];

    float* out = (float*)d_out;
    float* e_out = out + Bc * Nc * Cc;   // out first, then e_out

    k_wprep<<<8, 256>>>(We);
    k_proj<<<Bc * Nc, 64>>>(x, W, a_src, a_dst);
    k_edge<<<dim3(Nc / 64, Nc, Bc), 256>>>(e, a_edge, e_out);
    k_attn<<<Bc * Nc, 256>>>(adj, x, bias, out);
}